// round 10
// baseline (speedup 1.0000x reference)
#include <cuda_runtime.h>

// Problem constants (fixed by the dataset)
#define BB 16
#define TT 128
#define UU 64
#define VV 1024
#define CELLS (BB * TT * UU)      // 131072
#define NEGF   (-1e30f)
#define LOG2EF 1.4426950408889634f
#define LN2F   0.6931471805599453f

// Scratch (allocation-free rule: __device__ globals)
// lp tables stored PRE-SCALED by log2(e) (log2-domain DP).
__device__ float g_lpb[CELLS];    // lp_blank * log2e
__device__ float g_lpl[CELLS];    // lp_label * log2e (u < UU-1 valid)
__device__ float g_cost[BB];
__device__ int   g_ticket;        // last-block-done counter (zero-init; winner resets)

// ---------------------------------------------------------------------------
// FFMA-only expf (phase-1 bulk): avoids MUFU throughput wall at 134M ops.
// ---------------------------------------------------------------------------
__device__ __forceinline__ float fexp(float x) {
    const float C1    = 1.4426950408889634f;
    const float MAGIC = 12582912.0f;           // 1.5 * 2^23
    float z = fmaf(x, C1, MAGIC);
    float d = MAGIC - z;
    float f = fmaf(x, C1, d);
    float p = fmaf(f, 0.0096181291076285f, 0.0555041086648216f);
    p = fmaf(f, p, 0.2402265069591007f);
    p = fmaf(f, p, 0.6931471805599453f);
    p = fmaf(f, p, 1.0f);
    return __int_as_float(__float_as_int(p) + (__float_as_int(z) << 23));
}

__device__ __forceinline__ float fast_ex2(float x) {
    float r; asm("ex2.approx.ftz.f32 %0, %1;" : "=f"(r) : "f"(x)); return r;
}
__device__ __forceinline__ float fast_lg2(float x) {
    float r; asm("lg2.approx.ftz.f32 %0, %1;" : "=f"(r) : "f"(x)); return r;
}
__device__ __forceinline__ float lae2(float a, float b) {
    float M = fmaxf(a, b);
    return M + fast_lg2(fast_ex2(a - M) + fast_ex2(b - M));
}
// LAE3 with median trick: the max term contributes ex2(0)=1 exactly.
__device__ __forceinline__ float lae3(float x, float y, float z) {
    float lo = fminf(x, y), hi = fmaxf(x, y);
    float M  = fmaxf(hi, z);
    float e  = 1.0f + fast_ex2(lo - M) + fast_ex2(fminf(hi, z) - M);
    return M + fast_lg2(e);
}

// ---------------------------------------------------------------------------
// Phase 1: SOFTWARE-PIPELINED multi-cell lse. Each warp owns 8 consecutive
// (b,t,u) cells (32 KB contiguous). Next cell's 8 float4 loads are issued
// BEFORE the current cell's exp/reduce tail, so a full cell of loads is
// always in flight — removes the per-cell MLP=0 dead-time and 8x the CTA
// launch churn of the one-cell-per-warp version.
// ---------------------------------------------------------------------------
__global__ void __launch_bounds__(256) lse_kernel(const float* __restrict__ acts,
                                                  const int*   __restrict__ labels) {
    int gwarp = blockIdx.x * 8 + (threadIdx.x >> 5);
    int lane  = threadIdx.x & 31;
    int cell  = gwarp * 8;
    const float4* p = (const float4*)(acts + (size_t)cell * VV);

    float4 v[8];
#pragma unroll
    for (int j = 0; j < 8; j++)
        v[j] = __ldcs(&p[j * 32 + lane]);

#pragma unroll
    for (int i = 0; i < 8; i++, cell++) {
        float4 w[8];
        if (i < 7) {
#pragma unroll
            for (int j = 0; j < 8; j++)
                w[j] = __ldcs(&p[256 + j * 32 + lane]);   // next cell, in flight
        }

        float blank = v[0].x;                  // valid on lane 0 only
        float s0 = 0.f, s1 = 0.f, s2 = 0.f, s3 = 0.f;
#pragma unroll
        for (int j = 0; j < 8; j++) {
            s0 += fexp(v[j].x);
            s1 += fexp(v[j].y);
            s2 += fexp(v[j].z);
            s3 += fexp(v[j].w);
        }
        float s = (s0 + s1) + (s2 + s3);
#pragma unroll
        for (int o = 16; o; o >>= 1)
            s += __shfl_xor_sync(0xffffffffu, s, o);

        float lse2 = fast_lg2(s);              // log2-domain lse

        if (lane == 0) {
            g_lpb[cell] = fmaf(blank, LOG2EF, -lse2);
            int u = cell & (UU - 1);
            if (u < UU - 1) {
                int b   = cell >> 13;
                int lab = labels[b * (UU - 1) + u];
                g_lpl[cell] = fmaf(((const float*)p)[lab], LOG2EF, -lse2);
            }
        }

#pragma unroll
        for (int j = 0; j < 8; j++) v[j] = w[j];
        p += 256;                              // advance one cell (1024 floats)
    }
}

// ---------------------------------------------------------------------------
// Phase 2+3: BIDIRECTIONAL 2-diagonal-fused DP, one block per batch.
//  warp 0: forward alpha, 48 super-steps, diag 0 -> 96
//  warp 1: backward beta, 47 super-steps, diag 190 -> 96
//  meet:   loglike = LAE_u(alpha[96-u,u] + beta[96-u,u])
// Unchanged from R9 (11.8 us; loop ~3 us, remainder launch/stage overhead).
// ---------------------------------------------------------------------------
#define SF 48
#define SB 47

__global__ void __launch_bounds__(256) dp_kernel(float* __restrict__ out) {
    int b = blockIdx.x;
    extern __shared__ float sm[];
    float*  s_lpb  = sm;
    float*  s_lpl  = sm + 8192;
    float4* FW     = (float4*)(sm + 16384);
    float4* BW     = (float4*)(sm + 29184);
    float*  s_meet = sm + 41728;
    int tid = threadIdx.x;

    // Stage lp tables (float4, front-batched LDG).
    {
        const float4* gb = (const float4*)(g_lpb + b * TT * UU);
        const float4* gl = (const float4*)(g_lpl + b * TT * UU);
        float4* sb_ = (float4*)s_lpb;
        float4* sl_ = (float4*)s_lpl;
        float4 rb[8], rl[8];
#pragma unroll
        for (int i = 0; i < 8; i++) {
            rb[i] = __ldcg(&gb[i * 256 + tid]);
            rl[i] = __ldcg(&gl[i * 256 + tid]);
        }
#pragma unroll
        for (int i = 0; i < 8; i++) {
            sb_[i * 256 + tid] = rb[i];
            sl_[i * 256 + tid] = rl[i];
        }
    }
    __syncthreads();

    // ---- forward weights: j = s*64+u, s in [1,48] ----
    for (int j = 64 + tid; j < (SF + 1) * 64; j += 256) {
        int s = j >> 6, u = j & 63;
        int t = 2 * s - u;                     // in [-61, 96]
        int r0 = max(t, 0), r1 = max(t - 1, 0), r2 = max(t - 2, 0);
        int um1 = max(u - 1, 0), um2 = max(u - 2, 0);

        float b_r1u   = s_lpb[r1 * UU + u];
        float l_r0um1 = s_lpl[r0 * UU + um1];
        float A = s_lpb[r2 * UU + u] + b_r1u;
        float B = lae2(s_lpl[r1 * UU + um1] + b_r1u,
                       s_lpb[r1 * UU + um1] + l_r0um1);
        float C = s_lpl[r0 * UU + um2] + l_r0um1;
        if (u == 0) B = NEGF;
        if (u < 2)  C = NEGF;
        FW[j] = make_float4(A, B, C, 0.f);
    }
    // ---- backward weights: j = sb*64+u, sb in [1,47] ----
    for (int j = 64 + tid; j < (SB + 1) * 64; j += 256) {
        int sb = j >> 6, u = j & 63;
        int t = 190 - 2 * sb - u;              // >= 33 always; may be > 127
        int rt0 = min(t, TT - 1), rt1 = min(t + 1, TT - 1);
        int up1 = min(u + 1, UU - 1);

        float b00 = s_lpb[rt0 * UU + u],   b10 = s_lpb[rt1 * UU + u];
        float l00 = s_lpl[rt0 * UU + u],   l10 = s_lpl[rt1 * UU + u];
        float b01 = s_lpb[rt0 * UU + up1], l01 = s_lpl[rt0 * UU + up1];

        float A = b00 + b10;
        float B = lae2(b00 + l10, l00 + b01);
        float C = l00 + l01;
        if (u == 63) B = NEGF;
        if (u >= 62) C = NEGF;
        if (t > TT - 1) { A = NEGF; B = NEGF; C = NEGF; }
        BW[j] = make_float4(A, B, C, 0.f);
    }
    __syncthreads();

    int wid = tid >> 5, lane = tid & 31;
    int u_lo = lane * 2;

    if (wid == 0) {
        // ---------------- forward: 48 super-steps ----------------
        float a_lo = (lane == 0) ? 0.f : NEGF;
        float a_hi = NEGF;
        float nl_lo = __shfl_up_sync(0xffffffffu, a_lo, 1);
        float nl_hi = __shfl_up_sync(0xffffffffu, a_hi, 1);
        int W = 64 + u_lo;
        float4 w0 = FW[W], w1 = FW[W + 1];

#pragma unroll 2
        for (int s = 1; s < SF; s++) {
            float4 nw0 = FW[W + 64], nw1 = FW[W + 65];
            float n0 = lae3(a_lo + w0.x, nl_hi + w0.y, nl_lo + w0.z);
            float n1 = lae3(a_hi + w1.x, a_lo + w1.y, nl_hi + w1.z);
            a_lo = n0; a_hi = n1;
            nl_lo = __shfl_up_sync(0xffffffffu, a_lo, 1);
            nl_hi = __shfl_up_sync(0xffffffffu, a_hi, 1);
            w0 = nw0; w1 = nw1; W += 64;
        }
        {   // peel s = SF (no trailing shfl)
            float n0 = lae3(a_lo + w0.x, nl_hi + w0.y, nl_lo + w0.z);
            float n1 = lae3(a_hi + w1.x, a_lo + w1.y, nl_hi + w1.z);
            a_lo = n0; a_hi = n1;
        }
        s_meet[u_lo]     = a_lo;
        s_meet[u_lo + 1] = a_hi;
    } else if (wid == 1) {
        // ---------------- backward: 47 super-steps ----------------
        float b_lo = NEGF;
        float b_hi = (lane == 31) ? s_lpb[(TT - 1) * UU + (UU - 1)] : NEGF;
        float nr_lo = __shfl_down_sync(0xffffffffu, b_lo, 1);
        float nr_hi = __shfl_down_sync(0xffffffffu, b_hi, 1);
        int W = 64 + u_lo;
        float4 w0 = BW[W], w1 = BW[W + 1];

#pragma unroll 2
        for (int s = 1; s < SB; s++) {
            float4 nw0 = BW[W + 64], nw1 = BW[W + 65];
            float n0 = lae3(b_lo + w0.x, b_hi + w0.y, nr_lo + w0.z);
            float n1 = lae3(b_hi + w1.x, nr_lo + w1.y, nr_hi + w1.z);
            b_lo = n0; b_hi = n1;
            nr_lo = __shfl_down_sync(0xffffffffu, b_lo, 1);
            nr_hi = __shfl_down_sync(0xffffffffu, b_hi, 1);
            w0 = nw0; w1 = nw1; W += 64;
        }
        {   // peel s = SB
            float n0 = lae3(b_lo + w0.x, b_hi + w0.y, nr_lo + w0.z);
            float n1 = lae3(b_hi + w1.x, nr_lo + w1.y, nr_hi + w1.z);
            b_lo = n0; b_hi = n1;
        }
        s_meet[128 + u_lo]     = b_lo;
        s_meet[128 + u_lo + 1] = b_hi;
    }
    __syncthreads();

    // ---------------- combine on diag 96 + global mean ----------------
    if (wid == 0) {
        float v0 = s_meet[lane]      + s_meet[128 + lane];
        float v1 = s_meet[lane + 32] + s_meet[128 + lane + 32];
        float M = fmaxf(v0, v1);
#pragma unroll
        for (int o = 16; o; o >>= 1)
            M = fmaxf(M, __shfl_xor_sync(0xffffffffu, M, o));
        float e = fast_ex2(v0 - M) + fast_ex2(v1 - M);
#pragma unroll
        for (int o = 16; o; o >>= 1)
            e += __shfl_xor_sync(0xffffffffu, e, o);
        float ll2 = M + fast_lg2(e);           // log2-domain loglike

        int is_last = 0;
        if (lane == 0) {
            g_cost[b] = -ll2 * LN2F;
            __threadfence();
            is_last = (atomicAdd(&g_ticket, 1) == BB - 1);
        }
        is_last = __shfl_sync(0xffffffffu, is_last, 0);
        if (is_last) {
            float v = (lane < BB) ? __ldcg(&g_cost[lane]) : 0.f;
#pragma unroll
            for (int o = 16; o; o >>= 1)
                v += __shfl_xor_sync(0xffffffffu, v, o);
            if (lane == 0) {
                out[0] = v * (1.0f / BB);
                g_ticket = 0;                  // reset for next graph replay
            }
        }
    }
}

extern "C" void kernel_launch(void* const* d_in, const int* in_sizes, int n_in,
                              void* d_out, int out_size) {
    const float* acts   = (const float*)d_in[0];
    const int*   labels = (const int*)d_in[1];

    const int smem_bytes = 41984 * (int)sizeof(float);   // 167936
    cudaFuncSetAttribute(dp_kernel, cudaFuncAttributeMaxDynamicSharedMemorySize,
                         smem_bytes);

    lse_kernel<<<CELLS / 64, 256>>>(acts, labels);   // 2048 blocks, 8 cells/warp
    dp_kernel<<<BB, 256, smem_bytes>>>((float*)d_out);
}

// round 11
// speedup vs baseline: 1.0744x; 1.0744x over previous
#include <cuda_runtime.h>

// Problem constants (fixed by the dataset)
#define BB 16
#define TT 128
#define UU 64
#define VV 1024
#define CELLS (BB * TT * UU)      // 131072
#define NEGF   (-1e30f)
#define LOG2EF 1.4426950408889634f
#define LN2F   0.6931471805599453f

// Scratch (allocation-free rule: __device__ globals)
// lp tables stored PRE-SCALED by log2(e) (log2-domain DP).
__device__ float g_lpb[CELLS];    // lp_blank * log2e
__device__ float g_lpl[CELLS];    // lp_label * log2e (u < UU-1 valid)
__device__ float g_cost[BB];
__device__ int   g_ticket;        // last-block-done counter (zero-init; winner resets)

__device__ __forceinline__ float fast_ex2(float x) {
    float r; asm("ex2.approx.ftz.f32 %0, %1;" : "=f"(r) : "f"(x)); return r;
}
__device__ __forceinline__ float fast_lg2(float x) {
    float r; asm("lg2.approx.ftz.f32 %0, %1;" : "=f"(r) : "f"(x)); return r;
}
__device__ __forceinline__ float lae2(float a, float b) {
    float M = fmaxf(a, b);
    return M + fast_lg2(fast_ex2(a - M) + fast_ex2(b - M));
}
// LAE3 with median trick: the max term contributes ex2(0)=1 exactly.
__device__ __forceinline__ float lae3(float x, float y, float z) {
    float lo = fminf(x, y), hi = fmaxf(x, y);
    float M  = fmaxf(hi, z);
    float e  = 1.0f + fast_ex2(lo - M) + fast_ex2(fminf(hi, z) - M);
    return M + fast_lg2(e);
}

// ---------------------------------------------------------------------------
// Packed-pair exp via fma.rn.f32x2 (FFMA2, sm_103a PTX-only): same math as
// the scalar FFMA-only exp, two elements per instruction. Halves the fma-pipe
// issue pressure of the lse kernel so LDG issue slots stop contending.
// ---------------------------------------------------------------------------
__device__ __forceinline__ unsigned long long packf2(float a, float b) {
    unsigned long long r;
    asm("mov.b64 %0, {%1, %2};" : "=l"(r) : "f"(a), "f"(b));
    return r;
}
__device__ __forceinline__ void fexp_x2(unsigned long long X, float& r0, float& r1) {
    const float C1f   = 1.4426950408889634f;
    const float MAGIC = 12582912.0f;           // 1.5 * 2^23
    unsigned long long c1  = packf2(C1f, C1f);
    unsigned long long mg  = packf2(MAGIC, MAGIC);
    unsigned long long n1  = packf2(-1.0f, -1.0f);
    unsigned long long k4  = packf2(0.0096181291076285f, 0.0096181291076285f);
    unsigned long long k3  = packf2(0.0555041086648216f, 0.0555041086648216f);
    unsigned long long k2  = packf2(0.2402265069591007f, 0.2402265069591007f);
    unsigned long long k1  = packf2(0.6931471805599453f, 0.6931471805599453f);
    unsigned long long one = packf2(1.0f, 1.0f);

    unsigned long long z, d, f, p;
    asm("fma.rn.f32x2 %0, %1, %2, %3;" : "=l"(z) : "l"(X), "l"(c1), "l"(mg));
    asm("fma.rn.f32x2 %0, %1, %2, %3;" : "=l"(d) : "l"(z), "l"(n1), "l"(mg));  // MAGIC - z
    asm("fma.rn.f32x2 %0, %1, %2, %3;" : "=l"(f) : "l"(X), "l"(c1), "l"(d));
    asm("fma.rn.f32x2 %0, %1, %2, %3;" : "=l"(p) : "l"(f), "l"(k4), "l"(k3));
    asm("fma.rn.f32x2 %0, %1, %2, %3;" : "=l"(p) : "l"(f), "l"(p),  "l"(k2));
    asm("fma.rn.f32x2 %0, %1, %2, %3;" : "=l"(p) : "l"(f), "l"(p),  "l"(k1));
    asm("fma.rn.f32x2 %0, %1, %2, %3;" : "=l"(p) : "l"(f), "l"(p),  "l"(one));

    int p0, p1, z0, z1;
    asm("mov.b64 {%0, %1}, %2;" : "=r"(p0), "=r"(p1) : "l"(p));
    asm("mov.b64 {%0, %1}, %2;" : "=r"(z0), "=r"(z1) : "l"(z));
    r0 = __int_as_float(p0 + (z0 << 23));      // 2^k splice (exact)
    r1 = __int_as_float(p1 + (z1 << 23));
}

// ---------------------------------------------------------------------------
// Phase 1: one warp per (b,t,u) cell; 8 front-batched float4 streaming loads
// (R10 lesson: multi-cell pipelining blew registers/occupancy — reverted).
// Packed f32x2 exp math to cut issue pressure.
// ---------------------------------------------------------------------------
__global__ void __launch_bounds__(256) lse_kernel(const float* __restrict__ acts,
                                                  const int*   __restrict__ labels) {
    int warp = blockIdx.x * 8 + (threadIdx.x >> 5);
    int lane = threadIdx.x & 31;
    const float*  base = acts + (size_t)warp * VV;
    const float4* p4   = (const float4*)base;

    float4 v[8];
#pragma unroll
    for (int i = 0; i < 8; i++)
        v[i] = __ldcs(&p4[i * 32 + lane]);

    float blank = v[0].x;                      // valid on lane 0 only
    float s0 = 0.f, s1 = 0.f, s2 = 0.f, s3 = 0.f;
#pragma unroll
    for (int i = 0; i < 8; i++) {
        float e0, e1, e2, e3;
        fexp_x2(packf2(v[i].x, v[i].y), e0, e1);
        fexp_x2(packf2(v[i].z, v[i].w), e2, e3);
        s0 += e0; s1 += e1; s2 += e2; s3 += e3;
    }
    float s = (s0 + s1) + (s2 + s3);
#pragma unroll
    for (int o = 16; o; o >>= 1)
        s += __shfl_xor_sync(0xffffffffu, s, o);

    float lse2 = fast_lg2(s);                  // log2-domain lse

    if (lane == 0) {
        g_lpb[warp] = fmaf(blank, LOG2EF, -lse2);
        int u = warp & (UU - 1);
        if (u < UU - 1) {
            int b   = warp >> 13;
            int lab = labels[b * (UU - 1) + u];
            g_lpl[warp] = fmaf(base[lab], LOG2EF, -lse2);
        }
    }
}

// ---------------------------------------------------------------------------
// Phase 2+3: BIDIRECTIONAL 2-diagonal-fused DP, one block per batch.
//  warp 0: forward alpha, 48 super-steps, diag 0 -> 96
//  warp 1: backward beta, 47 super-steps, diag 190 -> 96
//  meet:   loglike = LAE_u(alpha[96-u,u] + beta[96-u,u])
// Unchanged from R9 (committed best: 11.8 us).
// ---------------------------------------------------------------------------
#define SF 48
#define SB 47

__global__ void __launch_bounds__(256) dp_kernel(float* __restrict__ out) {
    int b = blockIdx.x;
    extern __shared__ float sm[];
    float*  s_lpb  = sm;
    float*  s_lpl  = sm + 8192;
    float4* FW     = (float4*)(sm + 16384);
    float4* BW     = (float4*)(sm + 29184);
    float*  s_meet = sm + 41728;
    int tid = threadIdx.x;

    // Stage lp tables (float4, front-batched LDG).
    {
        const float4* gb = (const float4*)(g_lpb + b * TT * UU);
        const float4* gl = (const float4*)(g_lpl + b * TT * UU);
        float4* sb_ = (float4*)s_lpb;
        float4* sl_ = (float4*)s_lpl;
        float4 rb[8], rl[8];
#pragma unroll
        for (int i = 0; i < 8; i++) {
            rb[i] = __ldcg(&gb[i * 256 + tid]);
            rl[i] = __ldcg(&gl[i * 256 + tid]);
        }
#pragma unroll
        for (int i = 0; i < 8; i++) {
            sb_[i * 256 + tid] = rb[i];
            sl_[i * 256 + tid] = rl[i];
        }
    }
    __syncthreads();

    // ---- forward weights: j = s*64+u, s in [1,48] ----
    for (int j = 64 + tid; j < (SF + 1) * 64; j += 256) {
        int s = j >> 6, u = j & 63;
        int t = 2 * s - u;                     // in [-61, 96]
        int r0 = max(t, 0), r1 = max(t - 1, 0), r2 = max(t - 2, 0);
        int um1 = max(u - 1, 0), um2 = max(u - 2, 0);

        float b_r1u   = s_lpb[r1 * UU + u];
        float l_r0um1 = s_lpl[r0 * UU + um1];
        float A = s_lpb[r2 * UU + u] + b_r1u;
        float B = lae2(s_lpl[r1 * UU + um1] + b_r1u,
                       s_lpb[r1 * UU + um1] + l_r0um1);
        float C = s_lpl[r0 * UU + um2] + l_r0um1;
        if (u == 0) B = NEGF;
        if (u < 2)  C = NEGF;
        FW[j] = make_float4(A, B, C, 0.f);
    }
    // ---- backward weights: j = sb*64+u, sb in [1,47] ----
    for (int j = 64 + tid; j < (SB + 1) * 64; j += 256) {
        int sb = j >> 6, u = j & 63;
        int t = 190 - 2 * sb - u;              // >= 33 always; may be > 127
        int rt0 = min(t, TT - 1), rt1 = min(t + 1, TT - 1);
        int up1 = min(u + 1, UU - 1);

        float b00 = s_lpb[rt0 * UU + u],   b10 = s_lpb[rt1 * UU + u];
        float l00 = s_lpl[rt0 * UU + u],   l10 = s_lpl[rt1 * UU + u];
        float b01 = s_lpb[rt0 * UU + up1], l01 = s_lpl[rt0 * UU + up1];

        float A = b00 + b10;
        float B = lae2(b00 + l10, l00 + b01);
        float C = l00 + l01;
        if (u == 63) B = NEGF;
        if (u >= 62) C = NEGF;
        if (t > TT - 1) { A = NEGF; B = NEGF; C = NEGF; }
        BW[j] = make_float4(A, B, C, 0.f);
    }
    __syncthreads();

    int wid = tid >> 5, lane = tid & 31;
    int u_lo = lane * 2;

    if (wid == 0) {
        // ---------------- forward: 48 super-steps ----------------
        float a_lo = (lane == 0) ? 0.f : NEGF;
        float a_hi = NEGF;
        float nl_lo = __shfl_up_sync(0xffffffffu, a_lo, 1);
        float nl_hi = __shfl_up_sync(0xffffffffu, a_hi, 1);
        int W = 64 + u_lo;
        float4 w0 = FW[W], w1 = FW[W + 1];

#pragma unroll 2
        for (int s = 1; s < SF; s++) {
            float4 nw0 = FW[W + 64], nw1 = FW[W + 65];
            float n0 = lae3(a_lo + w0.x, nl_hi + w0.y, nl_lo + w0.z);
            float n1 = lae3(a_hi + w1.x, a_lo + w1.y, nl_hi + w1.z);
            a_lo = n0; a_hi = n1;
            nl_lo = __shfl_up_sync(0xffffffffu, a_lo, 1);
            nl_hi = __shfl_up_sync(0xffffffffu, a_hi, 1);
            w0 = nw0; w1 = nw1; W += 64;
        }
        {   // peel s = SF (no trailing shfl)
            float n0 = lae3(a_lo + w0.x, nl_hi + w0.y, nl_lo + w0.z);
            float n1 = lae3(a_hi + w1.x, a_lo + w1.y, nl_hi + w1.z);
            a_lo = n0; a_hi = n1;
        }
        s_meet[u_lo]     = a_lo;
        s_meet[u_lo + 1] = a_hi;
    } else if (wid == 1) {
        // ---------------- backward: 47 super-steps ----------------
        float b_lo = NEGF;
        float b_hi = (lane == 31) ? s_lpb[(TT - 1) * UU + (UU - 1)] : NEGF;
        float nr_lo = __shfl_down_sync(0xffffffffu, b_lo, 1);
        float nr_hi = __shfl_down_sync(0xffffffffu, b_hi, 1);
        int W = 64 + u_lo;
        float4 w0 = BW[W], w1 = BW[W + 1];

#pragma unroll 2
        for (int s = 1; s < SB; s++) {
            float4 nw0 = BW[W + 64], nw1 = BW[W + 65];
            float n0 = lae3(b_lo + w0.x, b_hi + w0.y, nr_lo + w0.z);
            float n1 = lae3(b_hi + w1.x, nr_lo + w1.y, nr_hi + w1.z);
            b_lo = n0; b_hi = n1;
            nr_lo = __shfl_down_sync(0xffffffffu, b_lo, 1);
            nr_hi = __shfl_down_sync(0xffffffffu, b_hi, 1);
            w0 = nw0; w1 = nw1; W += 64;
        }
        {   // peel s = SB
            float n0 = lae3(b_lo + w0.x, b_hi + w0.y, nr_lo + w0.z);
            float n1 = lae3(b_hi + w1.x, nr_lo + w1.y, nr_hi + w1.z);
            b_lo = n0; b_hi = n1;
        }
        s_meet[128 + u_lo]     = b_lo;
        s_meet[128 + u_lo + 1] = b_hi;
    }
    __syncthreads();

    // ---------------- combine on diag 96 + global mean ----------------
    if (wid == 0) {
        float v0 = s_meet[lane]      + s_meet[128 + lane];
        float v1 = s_meet[lane + 32] + s_meet[128 + lane + 32];
        float M = fmaxf(v0, v1);
#pragma unroll
        for (int o = 16; o; o >>= 1)
            M = fmaxf(M, __shfl_xor_sync(0xffffffffu, M, o));
        float e = fast_ex2(v0 - M) + fast_ex2(v1 - M);
#pragma unroll
        for (int o = 16; o; o >>= 1)
            e += __shfl_xor_sync(0xffffffffu, e, o);
        float ll2 = M + fast_lg2(e);           // log2-domain loglike

        int is_last = 0;
        if (lane == 0) {
            g_cost[b] = -ll2 * LN2F;
            __threadfence();
            is_last = (atomicAdd(&g_ticket, 1) == BB - 1);
        }
        is_last = __shfl_sync(0xffffffffu, is_last, 0);
        if (is_last) {
            float v = (lane < BB) ? __ldcg(&g_cost[lane]) : 0.f;
#pragma unroll
            for (int o = 16; o; o >>= 1)
                v += __shfl_xor_sync(0xffffffffu, v, o);
            if (lane == 0) {
                out[0] = v * (1.0f / BB);
                g_ticket = 0;                  // reset for next graph replay
            }
        }
    }
}

extern "C" void kernel_launch(void* const* d_in, const int* in_sizes, int n_in,
                              void* d_out, int out_size) {
    const float* acts   = (const float*)d_in[0];
    const int*   labels = (const int*)d_in[1];

    const int smem_bytes = 41984 * (int)sizeof(float);   // 167936
    cudaFuncSetAttribute(dp_kernel, cudaFuncAttributeMaxDynamicSharedMemorySize,
                         smem_bytes);

    lse_kernel<<<CELLS / 8, 256>>>(acts, labels);    // one cell per warp (reverted)
    dp_kernel<<<BB, 256, smem_bytes>>>((float*)d_out);
}

// round 12
// speedup vs baseline: 1.0911x; 1.0155x over previous
#include <cuda_runtime.h>

// Problem constants (fixed by the dataset)
#define BB 16
#define TT 128
#define UU 64
#define VV 1024
#define CELLS (BB * TT * UU)      // 131072
#define NEGF   (-1e30f)
#define LOG2EF 1.4426950408889634f
#define LN2F   0.6931471805599453f

// Scratch (allocation-free rule: __device__ globals)
// lp tables stored PRE-SCALED by log2(e) (log2-domain DP).
__device__ float g_lpb[CELLS];    // lp_blank * log2e
__device__ float g_lpl[CELLS];    // lp_label * log2e (u < UU-1 valid)
__device__ float g_cost[BB];
__device__ int   g_ticket;        // last-block-done counter (zero-init; winner resets)

__device__ __forceinline__ float fast_ex2(float x) {
    float r; asm("ex2.approx.ftz.f32 %0, %1;" : "=f"(r) : "f"(x)); return r;
}
__device__ __forceinline__ float fast_lg2(float x) {
    float r; asm("lg2.approx.ftz.f32 %0, %1;" : "=f"(r) : "f"(x)); return r;
}
__device__ __forceinline__ float lae2(float a, float b) {
    float M = fmaxf(a, b);
    return M + fast_lg2(fast_ex2(a - M) + fast_ex2(b - M));
}
// LAE3 with median trick: the max term contributes ex2(0)=1 exactly.
__device__ __forceinline__ float lae3(float x, float y, float z) {
    float lo = fminf(x, y), hi = fmaxf(x, y);
    float M  = fmaxf(hi, z);
    float e  = 1.0f + fast_ex2(lo - M) + fast_ex2(fminf(hi, z) - M);
    return M + fast_lg2(e);
}

// ---------------------------------------------------------------------------
// Packed-pair exp via fma.rn.f32x2 (FFMA2, sm_103a PTX-only).
// ---------------------------------------------------------------------------
__device__ __forceinline__ unsigned long long packf2(float a, float b) {
    unsigned long long r;
    asm("mov.b64 %0, {%1, %2};" : "=l"(r) : "f"(a), "f"(b));
    return r;
}
__device__ __forceinline__ void fexp_x2(unsigned long long X, float& r0, float& r1) {
    const float C1f   = 1.4426950408889634f;
    const float MAGIC = 12582912.0f;           // 1.5 * 2^23
    unsigned long long c1  = packf2(C1f, C1f);
    unsigned long long mg  = packf2(MAGIC, MAGIC);
    unsigned long long n1  = packf2(-1.0f, -1.0f);
    unsigned long long k4  = packf2(0.0096181291076285f, 0.0096181291076285f);
    unsigned long long k3  = packf2(0.0555041086648216f, 0.0555041086648216f);
    unsigned long long k2  = packf2(0.2402265069591007f, 0.2402265069591007f);
    unsigned long long k1  = packf2(0.6931471805599453f, 0.6931471805599453f);
    unsigned long long one = packf2(1.0f, 1.0f);

    unsigned long long z, d, f, p;
    asm("fma.rn.f32x2 %0, %1, %2, %3;" : "=l"(z) : "l"(X), "l"(c1), "l"(mg));
    asm("fma.rn.f32x2 %0, %1, %2, %3;" : "=l"(d) : "l"(z), "l"(n1), "l"(mg));  // MAGIC - z
    asm("fma.rn.f32x2 %0, %1, %2, %3;" : "=l"(f) : "l"(X), "l"(c1), "l"(d));
    asm("fma.rn.f32x2 %0, %1, %2, %3;" : "=l"(p) : "l"(f), "l"(k4), "l"(k3));
    asm("fma.rn.f32x2 %0, %1, %2, %3;" : "=l"(p) : "l"(f), "l"(p),  "l"(k2));
    asm("fma.rn.f32x2 %0, %1, %2, %3;" : "=l"(p) : "l"(f), "l"(p),  "l"(k1));
    asm("fma.rn.f32x2 %0, %1, %2, %3;" : "=l"(p) : "l"(f), "l"(p),  "l"(one));

    int p0, p1, z0, z1;
    asm("mov.b64 {%0, %1}, %2;" : "=r"(p0), "=r"(p1) : "l"(p));
    asm("mov.b64 {%0, %1}, %2;" : "=r"(z0), "=r"(z1) : "l"(z));
    r0 = __int_as_float(p0 + (z0 << 23));      // 2^k splice (exact)
    r1 = __int_as_float(p1 + (z1 << 23));
}

// ---------------------------------------------------------------------------
// Phase 1: one warp per (b,t,u) cell; 8 front-batched float4 streaming loads.
// At the LTS/DRAM cap (~6.86 TB/s) — structurally done. Triggers PDL at
// entry so the dp kernel's blocks are dispatched while this streams.
// ---------------------------------------------------------------------------
__global__ void __launch_bounds__(256) lse_kernel(const float* __restrict__ acts,
                                                  const int*   __restrict__ labels) {
#if __CUDA_ARCH__ >= 900
    if (threadIdx.x == 0) cudaTriggerProgrammaticLaunchCompletion();
#endif
    int warp = blockIdx.x * 8 + (threadIdx.x >> 5);
    int lane = threadIdx.x & 31;
    const float*  base = acts + (size_t)warp * VV;
    const float4* p4   = (const float4*)base;

    float4 v[8];
#pragma unroll
    for (int i = 0; i < 8; i++)
        v[i] = __ldcs(&p4[i * 32 + lane]);

    float blank = v[0].x;                      // valid on lane 0 only
    float s0 = 0.f, s1 = 0.f, s2 = 0.f, s3 = 0.f;
#pragma unroll
    for (int i = 0; i < 8; i++) {
        float e0, e1, e2, e3;
        fexp_x2(packf2(v[i].x, v[i].y), e0, e1);
        fexp_x2(packf2(v[i].z, v[i].w), e2, e3);
        s0 += e0; s1 += e1; s2 += e2; s3 += e3;
    }
    float s = (s0 + s1) + (s2 + s3);
#pragma unroll
    for (int o = 16; o; o >>= 1)
        s += __shfl_xor_sync(0xffffffffu, s, o);

    float lse2 = fast_lg2(s);                  // log2-domain lse

    if (lane == 0) {
        g_lpb[warp] = fmaf(blank, LOG2EF, -lse2);
        int u = warp & (UU - 1);
        if (u < UU - 1) {
            int b   = warp >> 13;
            int lab = labels[b * (UU - 1) + u];
            g_lpl[warp] = fmaf(base[lab], LOG2EF, -lse2);
        }
    }
}

// ---------------------------------------------------------------------------
// Phase 2+3: BIDIRECTIONAL 2-diagonal-fused DP, one block per batch.
// Launched with PDL: blocks are resident before lse finishes; the grid
// dependency sync releases them the moment lse's stores are visible —
// launch/dispatch latency is fully hidden under the lse stream.
//  warp 0: forward alpha, 48 super-steps, diag 0 -> 96
//  warp 1: backward beta, 47 super-steps, diag 190 -> 96
//  meet:   loglike = LAE_u(alpha[96-u,u] + beta[96-u,u])
// ---------------------------------------------------------------------------
#define SF 48
#define SB 47

__global__ void __launch_bounds__(256) dp_kernel(float* __restrict__ out) {
#if __CUDA_ARCH__ >= 900
    cudaGridDependencySynchronize();           // wait for lse stores to land
#endif
    int b = blockIdx.x;
    extern __shared__ float sm[];
    float*  s_lpb  = sm;
    float*  s_lpl  = sm + 8192;
    float4* FW     = (float4*)(sm + 16384);
    float4* BW     = (float4*)(sm + 29184);
    float*  s_meet = sm + 41728;
    int tid = threadIdx.x;

    // Stage lp tables (float4, front-batched LDG).
    {
        const float4* gb = (const float4*)(g_lpb + b * TT * UU);
        const float4* gl = (const float4*)(g_lpl + b * TT * UU);
        float4* sb_ = (float4*)s_lpb;
        float4* sl_ = (float4*)s_lpl;
        float4 rb[8], rl[8];
#pragma unroll
        for (int i = 0; i < 8; i++) {
            rb[i] = __ldcg(&gb[i * 256 + tid]);
            rl[i] = __ldcg(&gl[i * 256 + tid]);
        }
#pragma unroll
        for (int i = 0; i < 8; i++) {
            sb_[i * 256 + tid] = rb[i];
            sl_[i * 256 + tid] = rl[i];
        }
    }
    __syncthreads();

    // ---- forward weights: j = s*64+u, s in [1,48] ----
    for (int j = 64 + tid; j < (SF + 1) * 64; j += 256) {
        int s = j >> 6, u = j & 63;
        int t = 2 * s - u;                     // in [-61, 96]
        int r0 = max(t, 0), r1 = max(t - 1, 0), r2 = max(t - 2, 0);
        int um1 = max(u - 1, 0), um2 = max(u - 2, 0);

        float b_r1u   = s_lpb[r1 * UU + u];
        float l_r0um1 = s_lpl[r0 * UU + um1];
        float A = s_lpb[r2 * UU + u] + b_r1u;
        float B = lae2(s_lpl[r1 * UU + um1] + b_r1u,
                       s_lpb[r1 * UU + um1] + l_r0um1);
        float C = s_lpl[r0 * UU + um2] + l_r0um1;
        if (u == 0) B = NEGF;
        if (u < 2)  C = NEGF;
        FW[j] = make_float4(A, B, C, 0.f);
    }
    // ---- backward weights: j = sb*64+u, sb in [1,47] ----
    for (int j = 64 + tid; j < (SB + 1) * 64; j += 256) {
        int sb = j >> 6, u = j & 63;
        int t = 190 - 2 * sb - u;              // >= 33 always; may be > 127
        int rt0 = min(t, TT - 1), rt1 = min(t + 1, TT - 1);
        int up1 = min(u + 1, UU - 1);

        float b00 = s_lpb[rt0 * UU + u],   b10 = s_lpb[rt1 * UU + u];
        float l00 = s_lpl[rt0 * UU + u],   l10 = s_lpl[rt1 * UU + u];
        float b01 = s_lpb[rt0 * UU + up1], l01 = s_lpl[rt0 * UU + up1];

        float A = b00 + b10;
        float B = lae2(b00 + l10, l00 + b01);
        float C = l00 + l01;
        if (u == 63) B = NEGF;
        if (u >= 62) C = NEGF;
        if (t > TT - 1) { A = NEGF; B = NEGF; C = NEGF; }
        BW[j] = make_float4(A, B, C, 0.f);
    }
    __syncthreads();

    int wid = tid >> 5, lane = tid & 31;
    int u_lo = lane * 2;

    if (wid == 0) {
        // ---------------- forward: 48 super-steps ----------------
        float a_lo = (lane == 0) ? 0.f : NEGF;
        float a_hi = NEGF;
        float nl_lo = __shfl_up_sync(0xffffffffu, a_lo, 1);
        float nl_hi = __shfl_up_sync(0xffffffffu, a_hi, 1);
        int W = 64 + u_lo;
        float4 w0 = FW[W], w1 = FW[W + 1];

#pragma unroll 2
        for (int s = 1; s < SF; s++) {
            float4 nw0 = FW[W + 64], nw1 = FW[W + 65];
            float n0 = lae3(a_lo + w0.x, nl_hi + w0.y, nl_lo + w0.z);
            float n1 = lae3(a_hi + w1.x, a_lo + w1.y, nl_hi + w1.z);
            a_lo = n0; a_hi = n1;
            nl_lo = __shfl_up_sync(0xffffffffu, a_lo, 1);
            nl_hi = __shfl_up_sync(0xffffffffu, a_hi, 1);
            w0 = nw0; w1 = nw1; W += 64;
        }
        {   // peel s = SF (no trailing shfl)
            float n0 = lae3(a_lo + w0.x, nl_hi + w0.y, nl_lo + w0.z);
            float n1 = lae3(a_hi + w1.x, a_lo + w1.y, nl_hi + w1.z);
            a_lo = n0; a_hi = n1;
        }
        s_meet[u_lo]     = a_lo;
        s_meet[u_lo + 1] = a_hi;
    } else if (wid == 1) {
        // ---------------- backward: 47 super-steps ----------------
        float b_lo = NEGF;
        float b_hi = (lane == 31) ? s_lpb[(TT - 1) * UU + (UU - 1)] : NEGF;
        float nr_lo = __shfl_down_sync(0xffffffffu, b_lo, 1);
        float nr_hi = __shfl_down_sync(0xffffffffu, b_hi, 1);
        int W = 64 + u_lo;
        float4 w0 = BW[W], w1 = BW[W + 1];

#pragma unroll 2
        for (int s = 1; s < SB; s++) {
            float4 nw0 = BW[W + 64], nw1 = BW[W + 65];
            float n0 = lae3(b_lo + w0.x, b_hi + w0.y, nr_lo + w0.z);
            float n1 = lae3(b_hi + w1.x, nr_lo + w1.y, nr_hi + w1.z);
            b_lo = n0; b_hi = n1;
            nr_lo = __shfl_down_sync(0xffffffffu, b_lo, 1);
            nr_hi = __shfl_down_sync(0xffffffffu, b_hi, 1);
            w0 = nw0; w1 = nw1; W += 64;
        }
        {   // peel s = SB
            float n0 = lae3(b_lo + w0.x, b_hi + w0.y, nr_lo + w0.z);
            float n1 = lae3(b_hi + w1.x, nr_lo + w1.y, nr_hi + w1.z);
            b_lo = n0; b_hi = n1;
        }
        s_meet[128 + u_lo]     = b_lo;
        s_meet[128 + u_lo + 1] = b_hi;
    }
    __syncthreads();

    // ---------------- combine on diag 96 + global mean ----------------
    if (wid == 0) {
        float v0 = s_meet[lane]      + s_meet[128 + lane];
        float v1 = s_meet[lane + 32] + s_meet[128 + lane + 32];
        float M = fmaxf(v0, v1);
#pragma unroll
        for (int o = 16; o; o >>= 1)
            M = fmaxf(M, __shfl_xor_sync(0xffffffffu, M, o));
        float e = fast_ex2(v0 - M) + fast_ex2(v1 - M);
#pragma unroll
        for (int o = 16; o; o >>= 1)
            e += __shfl_xor_sync(0xffffffffu, e, o);
        float ll2 = M + fast_lg2(e);           // log2-domain loglike

        int is_last = 0;
        if (lane == 0) {
            g_cost[b] = -ll2 * LN2F;
            __threadfence();
            is_last = (atomicAdd(&g_ticket, 1) == BB - 1);
        }
        is_last = __shfl_sync(0xffffffffu, is_last, 0);
        if (is_last) {
            float v = (lane < BB) ? __ldcg(&g_cost[lane]) : 0.f;
#pragma unroll
            for (int o = 16; o; o >>= 1)
                v += __shfl_xor_sync(0xffffffffu, v, o);
            if (lane == 0) {
                out[0] = v * (1.0f / BB);
                g_ticket = 0;                  // reset for next graph replay
            }
        }
    }
}

extern "C" void kernel_launch(void* const* d_in, const int* in_sizes, int n_in,
                              void* d_out, int out_size) {
    const float* acts   = (const float*)d_in[0];
    const int*   labels = (const int*)d_in[1];

    const int smem_bytes = 41984 * (int)sizeof(float);   // 167936
    cudaFuncSetAttribute(dp_kernel, cudaFuncAttributeMaxDynamicSharedMemorySize,
                         smem_bytes);

    lse_kernel<<<CELLS / 8, 256>>>(acts, labels);

    // PDL launch: dp blocks dispatch while lse streams; the in-kernel grid
    // dependency sync provides the ordering.
    cudaLaunchConfig_t cfg = {};
    cfg.gridDim         = dim3(BB, 1, 1);
    cfg.blockDim        = dim3(256, 1, 1);
    cfg.dynamicSmemBytes = smem_bytes;
    cfg.stream          = 0;
    cudaLaunchAttribute attr[1];
    attr[0].id = cudaLaunchAttributeProgrammaticStreamSerialization;
    attr[0].val.programmaticStreamSerializationAllowed = 1;
    cfg.attrs    = attr;
    cfg.numAttrs = 1;
    cudaLaunchKernelEx(&cfg, dp_kernel, (float*)d_out);
}